// round 2
// baseline (speedup 1.0000x reference)
#include <cuda_runtime.h>
#include <cstdint>

#define NN 100000
#define NE 1600000
#define FDIM 64
#define NB_SCAN 98   // ceil(NN/1024)

// ---------------- scratch (no allocation allowed) ----------------
__device__ float g_B1[NN * FDIM];
__device__ float g_B2[NN * FDIM];
__device__ float g_B3[NN * FDIM];
__device__ float g_H [NN * FDIM];
__device__ int2  g_csr[NE];          // {src, weight-as-int-bits} sorted by dst
__device__ int   g_degS[NN];         // out-degree (indexed by src)
__device__ int   g_cntD[NN];         // in-count  (indexed by dst)
__device__ int   g_rowStart[NN + 1];
__device__ int   g_cursor[NN];
__device__ int   g_blockSums[128];
__device__ int   g_blockOffs[128];
__device__ float g_dinv[NN];

// buffer selector (host can't take addresses of __device__ globals)
__device__ __forceinline__ const float* pick(int s, const float* x) {
    switch (s) {
        case 1: return g_B1;
        case 2: return g_B2;
        case 3: return g_B3;
        case 4: return g_H;
        default: return x;
    }
}
__device__ __forceinline__ float* pickw(int s, float* o) {
    switch (s) {
        case 1: return g_B1;
        case 2: return g_B2;
        case 3: return g_B3;
        case 4: return g_H;
        default: return o;
    }
}

// ---------------- CSR build ----------------
__global__ void zero_kernel() {
    int i = blockIdx.x * blockDim.x + threadIdx.x;
    if (i < NN) { g_degS[i] = 0; g_cntD[i] = 0; }
}

__global__ void hist_kernel(const int* __restrict__ src, const int* __restrict__ dst) {
    for (int i = blockIdx.x * blockDim.x + threadIdx.x; i < NE; i += gridDim.x * blockDim.x) {
        atomicAdd(&g_degS[src[i]], 1);
        atomicAdd(&g_cntD[dst[i]], 1);
    }
}

__global__ void dinv_kernel() {
    int i = blockIdx.x * blockDim.x + threadIdx.x;
    if (i < NN) {
        int d = g_degS[i];
        g_dinv[i] = (d > 0) ? rsqrtf((float)d) : 0.0f;
    }
}

__global__ void scan1_kernel() {
    __shared__ int sb[1024];
    int i = blockIdx.x * 1024 + threadIdx.x;
    int v = (i < NN) ? g_cntD[i] : 0;
    sb[threadIdx.x] = v;
    __syncthreads();
    for (int off = 1; off < 1024; off <<= 1) {
        int t = (threadIdx.x >= off) ? sb[threadIdx.x - off] : 0;
        __syncthreads();
        sb[threadIdx.x] += t;
        __syncthreads();
    }
    if (i < NN) g_rowStart[i] = sb[threadIdx.x] - v;       // exclusive
    if (threadIdx.x == 1023) g_blockSums[blockIdx.x] = sb[1023];
}

__global__ void scan2_kernel() {   // 1 block, 128 threads
    __shared__ int sb[128];
    int v = (threadIdx.x < NB_SCAN) ? g_blockSums[threadIdx.x] : 0;
    sb[threadIdx.x] = v;
    __syncthreads();
    for (int off = 1; off < 128; off <<= 1) {
        int t = (threadIdx.x >= off) ? sb[threadIdx.x - off] : 0;
        __syncthreads();
        sb[threadIdx.x] += t;
        __syncthreads();
    }
    if (threadIdx.x < NB_SCAN) g_blockOffs[threadIdx.x] = sb[threadIdx.x] - v;
    if (threadIdx.x == 127) g_rowStart[NN] = sb[127];
}

__global__ void scan3_kernel() {
    int i = blockIdx.x * 1024 + threadIdx.x;
    if (i < NN) {
        int r = g_rowStart[i] + g_blockOffs[blockIdx.x];
        g_rowStart[i] = r;
        g_cursor[i]   = r;
    }
}

__global__ void scatter_kernel(const int* __restrict__ src, const int* __restrict__ dst) {
    for (int i = blockIdx.x * blockDim.x + threadIdx.x; i < NE; i += gridDim.x * blockDim.x) {
        int s = src[i], d = dst[i];
        float w = -g_dinv[s] * g_dinv[d];
        int p = atomicAdd(&g_cursor[d], 1);
        g_csr[p] = make_int2(s, __float_as_int(w));
    }
}

// ---------------- propagation: out = a * (L_hat @ h) + b * prev ----------------
// one warp per dst node; lane covers columns {2*lane, 2*lane+1} via float2
__global__ void __launch_bounds__(256) prop_kernel(
    const float* __restrict__ xin, int hsel, int psel, int osel, float a, float b)
{
    const float* h    = pick(hsel, xin);
    const float* prev = pick(psel, xin);
    float* out        = pickw(osel, nullptr);

    int gw   = (blockIdx.x * blockDim.x + threadIdx.x) >> 5;
    int lane = threadIdx.x & 31;
    if (gw >= NN) return;

    int s = g_rowStart[gw];
    int e = g_rowStart[gw + 1];

    float ax = 0.0f, ay = 0.0f;
    int j  = s;
    int e4 = s + ((e - s) & ~3);
    for (; j < e4; j += 4) {
        int2 c0 = g_csr[j + 0];
        int2 c1 = g_csr[j + 1];
        int2 c2 = g_csr[j + 2];
        int2 c3 = g_csr[j + 3];
        float2 v0 = *(const float2*)(h + (size_t)c0.x * FDIM + 2 * lane);
        float2 v1 = *(const float2*)(h + (size_t)c1.x * FDIM + 2 * lane);
        float2 v2 = *(const float2*)(h + (size_t)c2.x * FDIM + 2 * lane);
        float2 v3 = *(const float2*)(h + (size_t)c3.x * FDIM + 2 * lane);
        float w0 = __int_as_float(c0.y);
        float w1 = __int_as_float(c1.y);
        float w2 = __int_as_float(c2.y);
        float w3 = __int_as_float(c3.y);
        ax += w0 * v0.x; ay += w0 * v0.y;
        ax += w1 * v1.x; ay += w1 * v1.y;
        ax += w2 * v2.x; ay += w2 * v2.y;
        ax += w3 * v3.x; ay += w3 * v3.y;
    }
    for (; j < e; j++) {
        int2 c = g_csr[j];
        float2 v = *(const float2*)(h + (size_t)c.x * FDIM + 2 * lane);
        float w = __int_as_float(c.y);
        ax += w * v.x; ay += w * v.y;
    }

    float rx = a * ax, ry = a * ay;
    if (b != 0.0f) {
        float2 p = *(const float2*)(prev + (size_t)gw * FDIM + 2 * lane);
        rx += b * p.x; ry += b * p.y;
    }
    *(float2*)(out + (size_t)gw * FDIM + 2 * lane) = make_float2(rx, ry);
}

// ---------------- layer-1 combine: out = [relu] sum_k T_k @ W_k  (64 -> 64) ----------------
// 256 threads/block, 64 nodes/block, 4 threads per node (16 output cols each)
__global__ void __launch_bounds__(256) combine64_kernel(
    const float* __restrict__ xin, int s0, int s1, int s2, int s3,
    const float* __restrict__ W, int osel, int do_relu)
{
    __shared__ float sW[64 * 64];
    __shared__ float sT[64][68];   // pad 68: conflict-free & 16B-aligned rows

    const float* ts0 = pick(s0, xin);
    const float* ts1 = pick(s1, xin);
    const float* ts2 = pick(s2, xin);
    const float* ts3 = pick(s3, xin);
    float* out = pickw(osel, nullptr);

    int tid   = threadIdx.x;
    int nodeL = tid >> 2;
    int jq    = tid & 3;
    int n0    = blockIdx.x * 64;

    float acc[16];
#pragma unroll
    for (int q = 0; q < 16; q++) acc[q] = 0.0f;

#pragma unroll
    for (int k = 0; k < 4; k++) {
        const float* tk = (k == 0) ? ts0 : (k == 1) ? ts1 : (k == 2) ? ts2 : ts3;
        const float4* Wk4 = (const float4*)(W + k * 4096);
#pragma unroll
        for (int i = tid; i < 1024; i += 256) ((float4*)sW)[i] = Wk4[i];
        const float4* tk4 = (const float4*)tk;
#pragma unroll
        for (int i = tid; i < 1024; i += 256) {
            int node = i >> 4, c4 = i & 15;
            float4 v = make_float4(0.f, 0.f, 0.f, 0.f);
            if (n0 + node < NN) v = tk4[(size_t)(n0 + node) * 16 + c4];
            *(float4*)&sT[node][c4 * 4] = v;
        }
        __syncthreads();

#pragma unroll
        for (int i4 = 0; i4 < 16; i4++) {
            float4 t = *(const float4*)&sT[nodeL][i4 * 4];
#pragma unroll
            for (int c = 0; c < 4; c++) {
                float tv = (c == 0) ? t.x : (c == 1) ? t.y : (c == 2) ? t.z : t.w;
                const float4* wr = (const float4*)(sW + (i4 * 4 + c) * 64 + jq * 16);
                float4 w0 = wr[0], w1 = wr[1], w2 = wr[2], w3 = wr[3];
                acc[0]  += tv * w0.x; acc[1]  += tv * w0.y; acc[2]  += tv * w0.z; acc[3]  += tv * w0.w;
                acc[4]  += tv * w1.x; acc[5]  += tv * w1.y; acc[6]  += tv * w1.z; acc[7]  += tv * w1.w;
                acc[8]  += tv * w2.x; acc[9]  += tv * w2.y; acc[10] += tv * w2.z; acc[11] += tv * w2.w;
                acc[12] += tv * w3.x; acc[13] += tv * w3.y; acc[14] += tv * w3.z; acc[15] += tv * w3.w;
            }
        }
        __syncthreads();
    }

    int n = n0 + nodeL;
    if (n < NN) {
        float4* o4 = (float4*)(out + (size_t)n * 64 + jq * 16);
#pragma unroll
        for (int q4 = 0; q4 < 4; q4++) {
            float4 v = make_float4(acc[q4 * 4 + 0], acc[q4 * 4 + 1],
                                   acc[q4 * 4 + 2], acc[q4 * 4 + 3]);
            if (do_relu) {
                v.x = fmaxf(v.x, 0.f); v.y = fmaxf(v.y, 0.f);
                v.z = fmaxf(v.z, 0.f); v.w = fmaxf(v.w, 0.f);
            }
            o4[q4] = v;
        }
    }
}

// ---------------- layer-2 combine: out[n, 0..1] = sum_k U_k[n,:] @ W2_k ----------------
__global__ void __launch_bounds__(256) combine2_kernel(
    const float* __restrict__ W2, float* __restrict__ out)
{
    __shared__ float sW[512];   // (K=4, 64, 2)
    for (int i = threadIdx.x; i < 512; i += blockDim.x) sW[i] = W2[i];
    __syncthreads();

    int n = blockIdx.x * blockDim.x + threadIdx.x;
    if (n >= NN) return;

    float a0 = 0.0f, a1 = 0.0f;
#pragma unroll
    for (int k = 0; k < 4; k++) {
        const float* tk = (k == 0) ? g_H : (k == 1) ? g_B1 : (k == 2) ? g_B2 : g_B3;
        const float4* r = (const float4*)(tk + (size_t)n * 64);
        const float* w = sW + k * 128;
#pragma unroll
        for (int i4 = 0; i4 < 16; i4++) {
            float4 v = r[i4];
            int i = i4 * 4;
            a0 += v.x * w[i * 2]           + v.y * w[(i + 1) * 2]
                + v.z * w[(i + 2) * 2]     + v.w * w[(i + 3) * 2];
            a1 += v.x * w[i * 2 + 1]       + v.y * w[(i + 1) * 2 + 1]
                + v.z * w[(i + 2) * 2 + 1] + v.w * w[(i + 3) * 2 + 1];
        }
    }
    out[n * 2 + 0] = a0;
    out[n * 2 + 1] = a1;
}

// ---------------- launcher ----------------
extern "C" void kernel_launch(void* const* d_in, const int* in_sizes, int n_in,
                              void* d_out, int out_size)
{
    const float* x   = (const float*)d_in[0];
    const int*   ei  = (const int*)d_in[1];
    const int*   src = ei;
    const int*   dst = ei + NE;
    const float* W1  = (const float*)d_in[2];
    const float* W2  = (const float*)d_in[3];
    float* out = (float*)d_out;

    const int TB = 256;
    int gN  = (NN + TB - 1) / TB;
    int gP  = (NN * 32 + TB - 1) / TB;   // one warp per node
    int gC  = (NN + 63) / 64;
    int gS  = 1184;                      // grid-stride kernels: 8 blocks/SM

    // ---- CSR build (fresh every launch) ----
    zero_kernel<<<gN, TB>>>();
    hist_kernel<<<gS, TB>>>(src, dst);
    dinv_kernel<<<gN, TB>>>();
    scan1_kernel<<<NB_SCAN, 1024>>>();
    scan2_kernel<<<1, 128>>>();
    scan3_kernel<<<NB_SCAN, 1024>>>();
    scatter_kernel<<<gS, TB>>>(src, dst);

    // ---- layer 1: T1=prop(x); T2=2*prop(T1)-x; T3=2*prop(T2)-T1 ----
    prop_kernel<<<gP, TB>>>(x, 0, 0, 1, 1.0f,  0.0f);   // B1 = prop(x)
    prop_kernel<<<gP, TB>>>(x, 1, 0, 2, 2.0f, -1.0f);   // B2 = 2*prop(B1) - x
    prop_kernel<<<gP, TB>>>(x, 2, 1, 3, 2.0f, -1.0f);   // B3 = 2*prop(B2) - B1
    combine64_kernel<<<gC, TB>>>(x, 0, 1, 2, 3, W1, 4, 1);   // H = relu(sum)

    // ---- layer 2 (reuse B1..B3) ----
    prop_kernel<<<gP, TB>>>(x, 4, 4, 1, 1.0f,  0.0f);   // B1 = prop(H)
    prop_kernel<<<gP, TB>>>(x, 1, 4, 2, 2.0f, -1.0f);   // B2 = 2*prop(B1) - H
    prop_kernel<<<gP, TB>>>(x, 2, 1, 3, 2.0f, -1.0f);   // B3 = 2*prop(B2) - B1
    combine2_kernel<<<gN, TB>>>(W2, out);
}

// round 5
// speedup vs baseline: 1.2269x; 1.2269x over previous
#include <cuda_runtime.h>
#include <cstdint>

#define NN 100000
#define NE 1600000
#define FDIM 64
#define NB_SCAN 98   // ceil(NN/1024)

// ---------------- scratch (no allocation allowed) ----------------
__device__ float g_B1[NN * FDIM];
__device__ float g_B2[NN * FDIM];
__device__ float g_B3[NN * FDIM];
__device__ float g_H [NN * FDIM];
__device__ int2  g_csr[NE];          // {src, weight-as-int-bits} sorted by dst
__device__ int   g_degS[NN];         // out-degree (indexed by src)
__device__ int   g_cntD[NN];         // in-count  (indexed by dst)
__device__ int   g_rowStart[NN + 1];
__device__ int   g_cursor[NN];
__device__ int   g_blockSums[128];
__device__ int   g_blockOffs[128];
__device__ float g_dinv[NN];

__device__ __forceinline__ const float* pick(int s, const float* x) {
    switch (s) {
        case 1: return g_B1;
        case 2: return g_B2;
        case 3: return g_B3;
        case 4: return g_H;
        default: return x;
    }
}
__device__ __forceinline__ float* pickw(int s, float* o) {
    switch (s) {
        case 1: return g_B1;
        case 2: return g_B2;
        case 3: return g_B3;
        case 4: return g_H;
        default: return o;
    }
}

// ---------------- CSR build ----------------
__global__ void zero_kernel() {
    int i = blockIdx.x * blockDim.x + threadIdx.x;
    if (i < NN) { g_degS[i] = 0; g_cntD[i] = 0; }
}

__global__ void hist_kernel(const int* __restrict__ src, const int* __restrict__ dst) {
    for (int i = blockIdx.x * blockDim.x + threadIdx.x; i < NE; i += gridDim.x * blockDim.x) {
        atomicAdd(&g_degS[src[i]], 1);
        atomicAdd(&g_cntD[dst[i]], 1);
    }
}

__global__ void dinv_kernel() {
    int i = blockIdx.x * blockDim.x + threadIdx.x;
    if (i < NN) {
        int d = g_degS[i];
        g_dinv[i] = (d > 0) ? rsqrtf((float)d) : 0.0f;
    }
}

__global__ void scan1_kernel() {
    __shared__ int sb[1024];
    int i = blockIdx.x * 1024 + threadIdx.x;
    int v = (i < NN) ? g_cntD[i] : 0;
    sb[threadIdx.x] = v;
    __syncthreads();
    for (int off = 1; off < 1024; off <<= 1) {
        int t = (threadIdx.x >= off) ? sb[threadIdx.x - off] : 0;
        __syncthreads();
        sb[threadIdx.x] += t;
        __syncthreads();
    }
    if (i < NN) g_rowStart[i] = sb[threadIdx.x] - v;       // exclusive
    if (threadIdx.x == 1023) g_blockSums[blockIdx.x] = sb[1023];
}

__global__ void scan2_kernel() {   // 1 block, 128 threads
    __shared__ int sb[128];
    int v = (threadIdx.x < NB_SCAN) ? g_blockSums[threadIdx.x] : 0;
    sb[threadIdx.x] = v;
    __syncthreads();
    for (int off = 1; off < 128; off <<= 1) {
        int t = (threadIdx.x >= off) ? sb[threadIdx.x - off] : 0;
        __syncthreads();
        sb[threadIdx.x] += t;
        __syncthreads();
    }
    if (threadIdx.x < NB_SCAN) g_blockOffs[threadIdx.x] = sb[threadIdx.x] - v;
    if (threadIdx.x == 127) g_rowStart[NN] = sb[127];
}

__global__ void scan3_kernel() {
    int i = blockIdx.x * 1024 + threadIdx.x;
    if (i < NN) {
        int r = g_rowStart[i] + g_blockOffs[blockIdx.x];
        g_rowStart[i] = r;
        g_cursor[i]   = r;
    }
}

__global__ void scatter_kernel(const int* __restrict__ src, const int* __restrict__ dst) {
    for (int i = blockIdx.x * blockDim.x + threadIdx.x; i < NE; i += gridDim.x * blockDim.x) {
        int s = src[i], d = dst[i];
        float w = -g_dinv[s] * g_dinv[d];
        int p = atomicAdd(&g_cursor[d], 1);
        g_csr[p] = make_int2(s, __float_as_int(w));
    }
}

// ---------------- 64-wide propagation: out = a*(L_hat @ h) + b*prev ----------------
// 2 nodes per warp; 16 lanes/node; lane covers 4 cols via float4 (256B/edge in 1 LDG.128)
__global__ void __launch_bounds__(256) prop64_kernel(
    const float* __restrict__ xin, int hsel, int psel, int osel, float a, float b)
{
    const float* h    = pick(hsel, xin);
    const float* prev = pick(psel, xin);
    float* out        = pickw(osel, nullptr);

    int warp = (blockIdx.x * blockDim.x + threadIdx.x) >> 5;
    int lane = threadIdx.x & 31;
    int sub  = lane >> 4;          // node within warp
    int l16  = lane & 15;          // lane within node group
    int n    = warp * 2 + sub;
    if (n >= NN) return;

    int s = g_rowStart[n];
    int e = g_rowStart[n + 1];

    float4 acc = make_float4(0.f, 0.f, 0.f, 0.f);
    int j = s;
    // parity peel so int4 loads of g_csr are 16B-aligned (even index)
    if ((j & 1) && j < e) {
        int2 c = g_csr[j];
        float w = __int_as_float(c.y);
        float4 v = *(const float4*)(h + (size_t)c.x * FDIM + l16 * 4);
        acc.x += w * v.x; acc.y += w * v.y; acc.z += w * v.z; acc.w += w * v.w;
        j++;
    }
    int e4 = j + ((e - j) & ~3);
    for (; j < e4; j += 4) {
        int4 c01 = *(const int4*)&g_csr[j];
        int4 c23 = *(const int4*)&g_csr[j + 2];
        float4 v0 = *(const float4*)(h + (size_t)c01.x * FDIM + l16 * 4);
        float4 v1 = *(const float4*)(h + (size_t)c01.z * FDIM + l16 * 4);
        float4 v2 = *(const float4*)(h + (size_t)c23.x * FDIM + l16 * 4);
        float4 v3 = *(const float4*)(h + (size_t)c23.z * FDIM + l16 * 4);
        float w0 = __int_as_float(c01.y);
        float w1 = __int_as_float(c01.w);
        float w2 = __int_as_float(c23.y);
        float w3 = __int_as_float(c23.w);
        acc.x += w0 * v0.x; acc.y += w0 * v0.y; acc.z += w0 * v0.z; acc.w += w0 * v0.w;
        acc.x += w1 * v1.x; acc.y += w1 * v1.y; acc.z += w1 * v1.z; acc.w += w1 * v1.w;
        acc.x += w2 * v2.x; acc.y += w2 * v2.y; acc.z += w2 * v2.z; acc.w += w2 * v2.w;
        acc.x += w3 * v3.x; acc.y += w3 * v3.y; acc.z += w3 * v3.z; acc.w += w3 * v3.w;
    }
    for (; j < e; j++) {
        int2 c = g_csr[j];
        float w = __int_as_float(c.y);
        float4 v = *(const float4*)(h + (size_t)c.x * FDIM + l16 * 4);
        acc.x += w * v.x; acc.y += w * v.y; acc.z += w * v.z; acc.w += w * v.w;
    }

    float4 r = make_float4(a * acc.x, a * acc.y, a * acc.z, a * acc.w);
    if (b != 0.0f) {
        float4 p = *(const float4*)(prev + (size_t)n * FDIM + l16 * 4);
        r.x += b * p.x; r.y += b * p.y; r.z += b * p.z; r.w += b * p.w;
    }
    *(float4*)(out + (size_t)n * FDIM + l16 * 4) = r;
}

// ---------------- 8-wide propagation (layer 2 after W2 projection) ----------------
// 4 nodes per warp; 8 lanes/node; lane covers 1 col. 32B/edge (1 sector).
// fuse: last prop computes t3 and directly emits out[n,c] = t3[n,6+c]+t2[n,4+c]+t1[n,2+c]+Z[n,c]
__global__ void __launch_bounds__(256) prop8_kernel(
    int hsel, int psel, int osel, float a, float b, int fuse, float* __restrict__ fout)
{
    const float* h    = pick(hsel, nullptr);
    const float* prev = pick(psel, nullptr);
    float* out        = pickw(osel, nullptr);

    int warp = (blockIdx.x * blockDim.x + threadIdx.x) >> 5;
    int lane = threadIdx.x & 31;
    int sub  = lane >> 3;
    int l8   = lane & 7;
    int n    = warp * 4 + sub;     // NN % 4 == 0 -> all warps full
    if (n >= NN) return;

    int s = g_rowStart[n];
    int e = g_rowStart[n + 1];

    float acc = 0.0f;
    int j  = s;
    int e4 = s + ((e - s) & ~3);
    for (; j < e4; j += 4) {
        int2 c0 = g_csr[j + 0];
        int2 c1 = g_csr[j + 1];
        int2 c2 = g_csr[j + 2];
        int2 c3 = g_csr[j + 3];
        float v0 = h[(size_t)c0.x * 8 + l8];
        float v1 = h[(size_t)c1.x * 8 + l8];
        float v2 = h[(size_t)c2.x * 8 + l8];
        float v3 = h[(size_t)c3.x * 8 + l8];
        acc += __int_as_float(c0.y) * v0;
        acc += __int_as_float(c1.y) * v1;
        acc += __int_as_float(c2.y) * v2;
        acc += __int_as_float(c3.y) * v3;
    }
    for (; j < e; j++) {
        int2 c = g_csr[j];
        acc += __int_as_float(c.y) * h[(size_t)c.x * 8 + l8];
    }

    float r = a * acc;
    if (b != 0.0f) r += b * prev[(size_t)n * 8 + l8];

    if (!fuse) {
        out[(size_t)n * 8 + l8] = r;
    } else {
        // r = t3[n, l8]; pull col (6+c) of t3 into lanes c=0,1 of each subgroup
        float t3v = __shfl_sync(0xFFFFFFFFu, r, (lane & ~7) + 6 + l8);
        if (l8 < 2) {
            float o = t3v
                    + h   [(size_t)n * 8 + 4 + l8]   // t2[n,4+c]
                    + prev[(size_t)n * 8 + 2 + l8]   // t1[n,2+c]
                    + g_B1[(size_t)n * 8 + l8];      // Z[n,c] = t0 block
            fout[(size_t)n * 2 + l8] = o;
        }
    }
}

// ---------------- Z projection: Z[n, 2k+c] = sum_i H[n,i] * W2[k,i,c]  -> g_B1 [N,8] ----------------
__global__ void __launch_bounds__(256) zproj_kernel(const float* __restrict__ W2)
{
    __shared__ float sW[512];   // (K=4, 64, 2)
    for (int i = threadIdx.x; i < 512; i += blockDim.x) sW[i] = W2[i];
    __syncthreads();

    int n = blockIdx.x * blockDim.x + threadIdx.x;
    if (n >= NN) return;

    const float4* row = (const float4*)(g_H + (size_t)n * 64);
    float acc[8];
#pragma unroll
    for (int q = 0; q < 8; q++) acc[q] = 0.0f;

#pragma unroll
    for (int i4 = 0; i4 < 16; i4++) {
        float4 v = row[i4];
#pragma unroll
        for (int c = 0; c < 4; c++) {
            float hv = (c == 0) ? v.x : (c == 1) ? v.y : (c == 2) ? v.z : v.w;
            int i = i4 * 4 + c;
#pragma unroll
            for (int k = 0; k < 4; k++) {
                acc[2 * k + 0] += hv * sW[k * 128 + i * 2 + 0];
                acc[2 * k + 1] += hv * sW[k * 128 + i * 2 + 1];
            }
        }
    }
    float4* o = (float4*)(g_B1 + (size_t)n * 8);
    o[0] = make_float4(acc[0], acc[1], acc[2], acc[3]);
    o[1] = make_float4(acc[4], acc[5], acc[6], acc[7]);
}

// ---------------- layer-1 combine: H = relu(sum_k T_k @ W1_k)  (64 -> 64) ----------------
__global__ void __launch_bounds__(256) combine64_kernel(
    const float* __restrict__ xin, int s0, int s1, int s2, int s3,
    const float* __restrict__ W, int osel, int do_relu)
{
    __shared__ float sW[64 * 64];
    __shared__ float sT[64][68];

    const float* ts0 = pick(s0, xin);
    const float* ts1 = pick(s1, xin);
    const float* ts2 = pick(s2, xin);
    const float* ts3 = pick(s3, xin);
    float* out = pickw(osel, nullptr);

    int tid   = threadIdx.x;
    int nodeL = tid >> 2;
    int jq    = tid & 3;
    int n0    = blockIdx.x * 64;

    float acc[16];
#pragma unroll
    for (int q = 0; q < 16; q++) acc[q] = 0.0f;

#pragma unroll
    for (int k = 0; k < 4; k++) {
        const float* tk = (k == 0) ? ts0 : (k == 1) ? ts1 : (k == 2) ? ts2 : ts3;
        const float4* Wk4 = (const float4*)(W + k * 4096);
#pragma unroll
        for (int i = tid; i < 1024; i += 256) ((float4*)sW)[i] = Wk4[i];
        const float4* tk4 = (const float4*)tk;
#pragma unroll
        for (int i = tid; i < 1024; i += 256) {
            int node = i >> 4, c4 = i & 15;
            float4 v = make_float4(0.f, 0.f, 0.f, 0.f);
            if (n0 + node < NN) v = tk4[(size_t)(n0 + node) * 16 + c4];
            *(float4*)&sT[node][c4 * 4] = v;
        }
        __syncthreads();

#pragma unroll
        for (int i4 = 0; i4 < 16; i4++) {
            float4 t = *(const float4*)&sT[nodeL][i4 * 4];
#pragma unroll
            for (int c = 0; c < 4; c++) {
                float tv = (c == 0) ? t.x : (c == 1) ? t.y : (c == 2) ? t.z : t.w;
                const float4* wr = (const float4*)(sW + (i4 * 4 + c) * 64 + jq * 16);
                float4 w0 = wr[0], w1 = wr[1], w2 = wr[2], w3 = wr[3];
                acc[0]  += tv * w0.x; acc[1]  += tv * w0.y; acc[2]  += tv * w0.z; acc[3]  += tv * w0.w;
                acc[4]  += tv * w1.x; acc[5]  += tv * w1.y; acc[6]  += tv * w1.z; acc[7]  += tv * w1.w;
                acc[8]  += tv * w2.x; acc[9]  += tv * w2.y; acc[10] += tv * w2.z; acc[11] += tv * w2.w;
                acc[12] += tv * w3.x; acc[13] += tv * w3.y; acc[14] += tv * w3.z; acc[15] += tv * w3.w;
            }
        }
        __syncthreads();
    }

    int n = n0 + nodeL;
    if (n < NN) {
        float4* o4 = (float4*)(out + (size_t)n * 64 + jq * 16);
#pragma unroll
        for (int q4 = 0; q4 < 4; q4++) {
            float4 v = make_float4(acc[q4 * 4 + 0], acc[q4 * 4 + 1],
                                   acc[q4 * 4 + 2], acc[q4 * 4 + 3]);
            if (do_relu) {
                v.x = fmaxf(v.x, 0.f); v.y = fmaxf(v.y, 0.f);
                v.z = fmaxf(v.z, 0.f); v.w = fmaxf(v.w, 0.f);
            }
            o4[q4] = v;
        }
    }
}

// ---------------- launcher ----------------
extern "C" void kernel_launch(void* const* d_in, const int* in_sizes, int n_in,
                              void* d_out, int out_size)
{
    const float* x   = (const float*)d_in[0];
    const int*   ei  = (const int*)d_in[1];
    const int*   src = ei;
    const int*   dst = ei + NE;
    const float* W1  = (const float*)d_in[2];
    const float* W2  = (const float*)d_in[3];
    float* out = (float*)d_out;

    const int TB = 256;
    int gN  = (NN + TB - 1) / TB;
    int gP  = ((NN / 2) * 32 + TB - 1) / TB;   // 2 nodes/warp (64-wide)
    int g8  = ((NN / 4) * 32 + TB - 1) / TB;   // 4 nodes/warp (8-wide)
    int gC  = (NN + 63) / 64;
    int gS  = 1184;

    // ---- CSR build (fresh every launch) ----
    zero_kernel<<<gN, TB>>>();
    hist_kernel<<<gS, TB>>>(src, dst);
    dinv_kernel<<<gN, TB>>>();
    scan1_kernel<<<NB_SCAN, 1024>>>();
    scan2_kernel<<<1, 128>>>();
    scan3_kernel<<<NB_SCAN, 1024>>>();
    scatter_kernel<<<gS, TB>>>(src, dst);

    // ---- layer 1: T1=prop(x); T2=2*prop(T1)-x; T3=2*prop(T2)-T1; H=relu(sum Tk W1k) ----
    prop64_kernel<<<gP, TB>>>(x, 0, 0, 1, 1.0f,  0.0f);   // B1 = prop(x)
    prop64_kernel<<<gP, TB>>>(x, 1, 0, 2, 2.0f, -1.0f);   // B2 = 2*prop(B1) - x
    prop64_kernel<<<gP, TB>>>(x, 2, 1, 3, 2.0f, -1.0f);   // B3 = 2*prop(B2) - B1
    combine64_kernel<<<gC, TB>>>(x, 0, 1, 2, 3, W1, 4, 1);   // H = relu(sum)

    // ---- layer 2 (project first: prop on 8-wide) ----
    zproj_kernel<<<gN, TB>>>(W2);                              // B1 = Z = H @ [W2_k] packed
    prop8_kernel<<<g8, TB>>>(1, 1, 2, 1.0f,  0.0f, 0, nullptr); // B2 = t1 = L Z
    prop8_kernel<<<g8, TB>>>(2, 1, 3, 2.0f, -1.0f, 0, nullptr); // B3 = t2 = 2 L t1 - Z
    prop8_kernel<<<g8, TB>>>(3, 2, 0, 2.0f, -1.0f, 1, out);     // t3 fused + final sum -> out
}